// round 1
// baseline (speedup 1.0000x reference)
#include <cuda_runtime.h>
#include <math.h>

#define Dd 2048
#define Hh 1152
#define Kk 64
#define NAa 18
#define Rr 10

// ---------------- scratch (device globals: no allocation allowed) ----------
__device__ __align__(16) float d_z[Dd];
__device__ __align__(16) float d_s[Dd];
__device__ __align__(16) float d_gpart[4 * Dd];   // Whh_m@h_t + bih_m + bhh_m
__device__ __align__(16) float d_u[Hh];           // worker hidden output
__device__ __align__(16) float d_ghat[Dd];
__device__ float d_part_sq[256];                  // per-block sum(ghat^2)
__device__ float d_part_mv[256];                  // per-block sum(Wmv*ghat)
__device__ float d_w[Kk];
__device__ float d_cosv[Rr];

__device__ __forceinline__ float sigm(float x) { return 1.f / (1.f + expf(-x)); }

// warp dot product over NIT*32 float4s (lane-strided), result on all lanes
template <int NIT>
__device__ __forceinline__ float wdot(const float4* __restrict__ a,
                                      const float4* __restrict__ b, int lane) {
    float acc = 0.f;
#pragma unroll
    for (int i = 0; i < NIT; i++) {
        float4 x = a[lane + i * 32];
        float4 y = b[lane + i * 32];
        acc = fmaf(x.x, y.x, acc);
        acc = fmaf(x.y, y.y, acc);
        acc = fmaf(x.z, y.z, acc);
        acc = fmaf(x.w, y.w, acc);
    }
#pragma unroll
    for (int o = 16; o; o >>= 1) acc += __shfl_xor_sync(0xffffffffu, acc, o);
    return acc;
}

// ---------------- K1: z = relu(Wp @ x + bp) --------------------------------
__global__ void k1_percept(const float* __restrict__ x,
                           const float* __restrict__ Wp,
                           const float* __restrict__ bp) {
    float x0 = x[0], x1 = x[1];
    for (int i = threadIdx.x; i < Dd; i += 256) {
        float v = fmaf(Wp[2 * i], x0, fmaf(Wp[2 * i + 1], x1, bp[i]));
        d_z[i] = fmaxf(v, 0.f);
    }
}

// ---------------- K2: s, manager partial gates, full worker LSTM -----------
// blocks [0,256):    s = relu(Wms@z + bms)                 (2048 rows, 8/blk)
// blocks [256,1280): gpart = Whh_m@hn_m[tick] + bih + bhh  (8192 rows, 8/blk)
// blocks [1280,1424): worker unit j -> u[j]                (1152 units, 8/blk)
__global__ void __launch_bounds__(256)
k2_wave(const float* __restrict__ Wms, const float* __restrict__ bms,
        const float* __restrict__ Whh_m, const float* __restrict__ bih_m,
        const float* __restrict__ bhh_m, const float* __restrict__ hn_m,
        const float* __restrict__ Wih_w, const float* __restrict__ Whh_w,
        const float* __restrict__ bih_w, const float* __restrict__ bhh_w,
        const float* __restrict__ hn_w, const float* __restrict__ cn_w,
        const int* __restrict__ tickp) {
    const int warp = threadIdx.x >> 5, lane = threadIdx.x & 31;
    const int b = blockIdx.x;
    if (b < 256) {
        int row = b * 8 + warp;
        float v = wdot<16>((const float4*)(Wms + (size_t)row * Dd),
                           (const float4*)d_z, lane);
        if (!lane) d_s[row] = fmaxf(v + bms[row], 0.f);
    } else if (b < 1280) {
        int row = (b - 256) * 8 + warp;
        int tick = *tickp;
        const float4* hv = (const float4*)(hn_m + (size_t)tick * Dd);
        float v = wdot<16>((const float4*)(Whh_m + (size_t)row * Dd), hv, lane);
        if (!lane) d_gpart[row] = v + bih_m[row] + bhh_m[row];
    } else {
        int j = (b - 1280) * 8 + warp;  // worker unit
        float g[4];
#pragma unroll
        for (int q = 0; q < 4; q++) {
            int row = j + q * Hh;
            float a = wdot<16>((const float4*)(Wih_w + (size_t)row * Dd),
                               (const float4*)d_z, lane);
            float c = wdot<9>((const float4*)(Whh_w + (size_t)row * Hh),
                              (const float4*)hn_w, lane);
            g[q] = a + c + bih_w[row] + bhh_w[row];
        }
        if (!lane) {
            float ig = sigm(g[0]), fg = sigm(g[1]);
            float gg = tanhf(g[2]), og = sigm(g[3]);
            float c2 = fmaf(fg, cn_w[j], ig * gg);
            d_u[j] = og * tanhf(c2);
        }
    }
}

// ---------------- K3: manager LSTM finish + ghat + partial reductions ------
__global__ void __launch_bounds__(256)
k3_manager(const float* __restrict__ Wih_m, const float* __restrict__ hn_m,
           const float* __restrict__ cn_m, const float* __restrict__ Wmv,
           const int* __restrict__ tickp) {
    const int warp = threadIdx.x >> 5, lane = threadIdx.x & 31;
    const int i = blockIdx.x * 8 + warp;  // manager unit
    const int tick = *tickp;
    float g[4];
#pragma unroll
    for (int q = 0; q < 4; q++) {
        int row = i + q * Dd;
        g[q] = wdot<16>((const float4*)(Wih_m + (size_t)row * Dd),
                        (const float4*)d_s, lane) + d_gpart[row];
    }
    __shared__ float s1[8], s2[8];
    if (!lane) {
        float ig = sigm(g[0]), fg = sigm(g[1]);
        float gg = tanhf(g[2]), og = sigm(g[3]);
        float c2 = fmaf(fg, cn_m[(size_t)tick * Dd + i], ig * gg);
        float hnew = og * tanhf(c2);
        float hs = hnew;
#pragma unroll
        for (int r = 0; r < Rr; r++)
            if (r != tick) hs += hn_m[(size_t)r * Dd + i];
        float gh = hs * 0.1f;
        d_ghat[i] = gh;
        s1[warp] = gh * gh;
        s2[warp] = gh * Wmv[i];
    }
    __syncthreads();
    if (threadIdx.x == 0) {
        float a = 0.f, c = 0.f;
#pragma unroll
        for (int q = 0; q < 8; q++) { a += s1[q]; c += s2[q]; }
        d_part_sq[blockIdx.x] = a;
        d_part_mv[blockIdx.x] = c;
    }
}

// ---------------- K4: w = Wphi @ gsum ; cosine terms -----------------------
// blocks 0-7: 8 w-rows each. blocks 8-9: cosine rows (warp r / r+8).
__global__ void __launch_bounds__(256)
k4_goals(const float* __restrict__ Wphi, const float* __restrict__ goals,
         const float* __restrict__ states) {
    const int tid = threadIdx.x;
    const int warp = tid >> 5, lane = tid & 31;
    __shared__ float red[256];
    __shared__ __align__(16) float gsum[Dd];

    // deterministic re-reduction of ||ghat||^2 (256 partials)
    red[tid] = d_part_sq[tid];
    __syncthreads();
    for (int s = 128; s; s >>= 1) {
        if (tid < s) red[tid] += red[tid + s];
        __syncthreads();
    }
    const float inv_norm = 1.f / fmaxf(sqrtf(red[0]), 1e-12f);
    __syncthreads();

    if (blockIdx.x < 8) {
        for (int d = tid; d < Dd; d += 256) {
            float v = d_ghat[d] * inv_norm;  // g contribution
#pragma unroll
            for (int r = 1; r < Rr; r++) v += goals[(size_t)r * Dd + d];
            gsum[d] = v;
        }
        __syncthreads();
        int k = blockIdx.x * 8 + warp;
        float v = wdot<16>((const float4*)(Wphi + (size_t)k * Dd),
                           (const float4*)gsum, lane);
        if (!lane) d_w[k] = v;
    } else {
        int r = (blockIdx.x - 8) * 8 + warp;
        if (r < Rr) {
            const float* st = states + (size_t)(r + 1) * Dd;
            const float* gl = goals + (size_t)(r + 1) * Dd;
            float num = 0.f, dd = 0.f, gg = 0.f;
            for (int d = lane; d < Dd; d += 32) {
                float diff = d_s[d] - st[d];
                float go = (r < Rr - 1) ? gl[d] : d_ghat[d] * inv_norm;
                num = fmaf(diff, go, num);
                dd = fmaf(diff, diff, dd);
                gg = fmaf(go, go, gg);
            }
#pragma unroll
            for (int o = 16; o; o >>= 1) {
                num += __shfl_xor_sync(0xffffffffu, num, o);
                dd += __shfl_xor_sync(0xffffffffu, dd, o);
                gg += __shfl_xor_sync(0xffffffffu, gg, o);
            }
            if (!lane)
                d_cosv[r] = num / (fmaxf(sqrtf(dd), 1e-8f) *
                                   fmaxf(sqrtf(gg), 1e-8f));
        }
    }
}

// ---------------- K5: outputs ----------------------------------------------
// out layout: [0:18] logits, [18] w_intrinsic_reward, [19] w_value, [20] m_value
__global__ void __launch_bounds__(256)
k5_final(const float* __restrict__ bmv, const float* __restrict__ Wc,
         const float* __restrict__ bc, float* __restrict__ out) {
    const int tid = threadIdx.x;
    __shared__ float red[256];

    // m_value = sum(Wmv*ghat) + bmv
    red[tid] = d_part_mv[tid];
    __syncthreads();
    for (int s = 128; s; s >>= 1) {
        if (tid < s) red[tid] += red[tid + s];
        __syncthreads();
    }
    if (tid == 0) out[20] = red[0] + bmv[0];
    __syncthreads();

    // w_value = Wc @ u + bc
    float wv = 0.f;
    for (int j = tid; j < Hh; j += 256) wv = fmaf(d_u[j], Wc[j], wv);
    red[tid] = wv;
    __syncthreads();
    for (int s = 128; s; s >>= 1) {
        if (tid < s) red[tid] += red[tid + s];
        __syncthreads();
    }
    if (tid == 0) out[19] = red[0] + bc[0];

    // logits
    if (tid < NAa) {
        float a = 0.f;
#pragma unroll
        for (int k = 0; k < Kk; k++) a = fmaf(d_u[tid * Kk + k], d_w[k], a);
        out[tid] = a;
    }

    // intrinsic reward = D * sum(cos) / C
    if (tid == 32) {
        float cs = 0.f;
#pragma unroll
        for (int r = 0; r < Rr; r++) cs += d_cosv[r];
        out[18] = 2048.f * cs * 0.1f;
    }
}

// ---------------- launch -----------------------------------------------------
extern "C" void kernel_launch(void* const* d_in, const int* in_sizes, int n_in,
                              void* d_out, int out_size) {
    const float* x      = (const float*)d_in[0];
    const float* Wp     = (const float*)d_in[1];
    const float* bp     = (const float*)d_in[2];
    const float* Wms    = (const float*)d_in[3];
    const float* bms    = (const float*)d_in[4];
    const float* Wih_m  = (const float*)d_in[5];
    const float* Whh_m  = (const float*)d_in[6];
    const float* bih_m  = (const float*)d_in[7];
    const float* bhh_m  = (const float*)d_in[8];
    const float* hn_m   = (const float*)d_in[9];
    const float* cn_m   = (const float*)d_in[10];
    const float* Wmv    = (const float*)d_in[11];
    const float* bmv    = (const float*)d_in[12];
    const float* Wih_w  = (const float*)d_in[13];
    const float* Whh_w  = (const float*)d_in[14];
    const float* bih_w  = (const float*)d_in[15];
    const float* bhh_w  = (const float*)d_in[16];
    const float* hn_w   = (const float*)d_in[17];
    const float* cn_w   = (const float*)d_in[18];
    const float* Wphi   = (const float*)d_in[19];
    const float* Wc     = (const float*)d_in[20];
    const float* bc     = (const float*)d_in[21];
    const float* states = (const float*)d_in[22];
    const float* goals  = (const float*)d_in[23];
    const int*   tick   = (const int*)d_in[24];
    float* out = (float*)d_out;

    k1_percept<<<1, 256>>>(x, Wp, bp);
    k2_wave<<<1424, 256>>>(Wms, bms, Whh_m, bih_m, bhh_m, hn_m,
                           Wih_w, Whh_w, bih_w, bhh_w, hn_w, cn_w, tick);
    k3_manager<<<256, 256>>>(Wih_m, hn_m, cn_m, Wmv, tick);
    k4_goals<<<10, 256>>>(Wphi, goals, states);
    k5_final<<<1, 256>>>(bmv, Wc, bc, out);
}

// round 3
// speedup vs baseline: 1.0330x; 1.0330x over previous
#include <cuda_runtime.h>
#include <math.h>

#define Dd 2048
#define Hh 1152
#define Kk 64
#define NAa 18
#define Rr 10

// ---------------- scratch (device globals) ----------------------------------
__device__ __align__(16) float d_s[Dd];
__device__ __align__(16) float d_u[Hh];
__device__ __align__(16) float d_ghat[Dd];
__device__ __align__(16) float d_T[NAa * Dd];     // u_resh @ Wphi
__device__ float d_part_sq[256];
__device__ float d_part_mv[256];
__device__ float d_cosv[Rr];                      // r = 0..8 filled in K3
__device__ float d_wval;

__device__ __forceinline__ float sigm(float x) { return 1.f / (1.f + expf(-x)); }

// warp dot over NIT*32 float4s (lane-strided), result on all lanes
template <int NIT>
__device__ __forceinline__ float wdot(const float4* __restrict__ a,
                                      const float4* __restrict__ b, int lane) {
    float acc = 0.f;
#pragma unroll
    for (int i = 0; i < NIT; i++) {
        float4 x = a[lane + i * 32];
        float4 y = b[lane + i * 32];
        acc = fmaf(x.x, y.x, acc);
        acc = fmaf(x.y, y.y, acc);
        acc = fmaf(x.z, y.z, acc);
        acc = fmaf(x.w, y.w, acc);
    }
#pragma unroll
    for (int o = 16; o; o >>= 1) acc += __shfl_xor_sync(0xffffffffu, acc, o);
    return acc;
}

// ---------------- K2: s = relu(Wms@z), worker LSTM (z recomputed in smem) ---
// blocks [0,256):   s rows (8 per block)
// blocks [256,400): worker units (8 per block)
__global__ void __launch_bounds__(256)
k2_wave(const float* __restrict__ x, const float* __restrict__ Wp,
        const float* __restrict__ bp, const float* __restrict__ Wms,
        const float* __restrict__ bms, const float* __restrict__ Wih_w,
        const float* __restrict__ Whh_w, const float* __restrict__ bih_w,
        const float* __restrict__ bhh_w, const float* __restrict__ hn_w,
        const float* __restrict__ cn_w) {
    __shared__ __align__(16) float zs[Dd];
    {
        float x0 = x[0], x1 = x[1];
        for (int i = threadIdx.x; i < Dd; i += 256) {
            float v = fmaf(Wp[2 * i], x0, fmaf(Wp[2 * i + 1], x1, bp[i]));
            zs[i] = fmaxf(v, 0.f);
        }
    }
    __syncthreads();
    const int warp = threadIdx.x >> 5, lane = threadIdx.x & 31;
    const int b = blockIdx.x;
    if (b < 256) {
        int row = b * 8 + warp;
        float v = wdot<16>((const float4*)(Wms + (size_t)row * Dd),
                           (const float4*)zs, lane);
        if (!lane) d_s[row] = fmaxf(v + bms[row], 0.f);
    } else {
        int j = (b - 256) * 8 + warp;  // worker unit
        float g[4];
#pragma unroll
        for (int q = 0; q < 4; q++) {
            int row = j + q * Hh;
            float a = wdot<16>((const float4*)(Wih_w + (size_t)row * Dd),
                               (const float4*)zs, lane);
            float c = wdot<9>((const float4*)(Whh_w + (size_t)row * Hh),
                              (const float4*)hn_w, lane);
            g[q] = a + c + bih_w[row] + bhh_w[row];
        }
        if (!lane) {
            float ig = sigm(g[0]), fg = sigm(g[1]);
            float gg = tanhf(g[2]), og = sigm(g[3]);
            float c2 = fmaf(fg, cn_w[j], ig * gg);
            d_u[j] = og * tanhf(c2);
        }
    }
}

// ---------------- K3: manager full gates + ghat; T = u@Wphi; 9 cosines; wv --
// blocks [0,256):   manager units (8/blk): 4 Wih_m rows + 4 Whh_m rows each
// blocks [256,274): T row a = b-256
// block  274:       cosines r=0..8 (warp handles r = warp, warp+8)
// block  275:       w_value = Wc@u + bc
__global__ void __launch_bounds__(256)
k3_wave(const float* __restrict__ Wih_m, const float* __restrict__ Whh_m,
        const float* __restrict__ bih_m, const float* __restrict__ bhh_m,
        const float* __restrict__ hn_m, const float* __restrict__ cn_m,
        const float* __restrict__ Wmv, const float* __restrict__ Wphi,
        const float* __restrict__ goals, const float* __restrict__ states,
        const float* __restrict__ Wc, const float* __restrict__ bc,
        const int* __restrict__ tickp) {
    const int tid = threadIdx.x;
    const int warp = tid >> 5, lane = tid & 31;
    const int b = blockIdx.x;

    if (b < 256) {
        const int i = b * 8 + warp;
        const int tick = *tickp;
        const float4* hv = (const float4*)(hn_m + (size_t)tick * Dd);
        float g[4];
#pragma unroll
        for (int q = 0; q < 4; q++) {
            int row = i + q * Dd;
            float a = wdot<16>((const float4*)(Wih_m + (size_t)row * Dd),
                               (const float4*)d_s, lane);
            float c = wdot<16>((const float4*)(Whh_m + (size_t)row * Dd), hv,
                               lane);
            g[q] = a + c + bih_m[row] + bhh_m[row];
        }
        __shared__ float s1[8], s2[8];
        if (!lane) {
            float ig = sigm(g[0]), fg = sigm(g[1]);
            float gg = tanhf(g[2]), og = sigm(g[3]);
            float c2 = fmaf(fg, cn_m[(size_t)tick * Dd + i], ig * gg);
            float hnew = og * tanhf(c2);
            float hs = hnew;
#pragma unroll
            for (int r = 0; r < Rr; r++)
                if (r != tick) hs += hn_m[(size_t)r * Dd + i];
            float gh = hs * 0.1f;
            d_ghat[i] = gh;
            s1[warp] = gh * gh;
            s2[warp] = gh * Wmv[i];
        }
        __syncthreads();
        if (tid == 0) {
            float a = 0.f, c = 0.f;
#pragma unroll
            for (int q = 0; q < 8; q++) { a += s1[q]; c += s2[q]; }
            d_part_sq[b] = a;
            d_part_mv[b] = c;
        }
    } else if (b < 256 + NAa) {
        const int a = b - 256;
        __shared__ float us[Kk];
        if (tid < Kk) us[tid] = d_u[a * Kk + tid];
        __syncthreads();
        for (int d = tid; d < Dd; d += 256) {
            float acc = 0.f;
#pragma unroll
            for (int k = 0; k < Kk; k++)
                acc = fmaf(us[k], Wphi[(size_t)k * Dd + d], acc);
            d_T[(size_t)a * Dd + d] = acc;
        }
    } else if (b == 256 + NAa) {
        // cosines r = 0..8 (independent of g); 8 warps cover 9 rows
        for (int r = warp; r < Rr - 1; r += 8) {
            const float* st = states + (size_t)(r + 1) * Dd;
            const float* gl = goals + (size_t)(r + 1) * Dd;
            float num = 0.f, dd = 0.f, gg = 0.f;
            for (int d = lane; d < Dd; d += 32) {
                float diff = d_s[d] - st[d];
                float go = gl[d];
                num = fmaf(diff, go, num);
                dd = fmaf(diff, diff, dd);
                gg = fmaf(go, go, gg);
            }
#pragma unroll
            for (int o = 16; o; o >>= 1) {
                num += __shfl_xor_sync(0xffffffffu, num, o);
                dd += __shfl_xor_sync(0xffffffffu, dd, o);
                gg += __shfl_xor_sync(0xffffffffu, gg, o);
            }
            if (!lane)
                d_cosv[r] = num / (fmaxf(sqrtf(dd), 1e-8f) *
                                   fmaxf(sqrtf(gg), 1e-8f));
        }
    } else {
        // w_value
        __shared__ float red[256];
        float wv = 0.f;
        for (int j = tid; j < Hh; j += 256) wv = fmaf(d_u[j], Wc[j], wv);
        red[tid] = wv;
        __syncthreads();
        for (int s = 128; s; s >>= 1) {
            if (tid < s) red[tid] += red[tid + s];
            __syncthreads();
        }
        if (tid == 0) d_wval = red[0] + bc[0];
    }
}

// ---------------- K4: final (1 block, 640 threads) ---------------------------
// out: [0:18] logits, [18] intrinsic, [19] w_value, [20] m_value
__global__ void __launch_bounds__(640)
k4_final(const float* __restrict__ goals, const float* __restrict__ states,
         const float* __restrict__ bmv, float* __restrict__ out) {
    const int tid = threadIdx.x;
    const int warp = tid >> 5, lane = tid & 31;
    __shared__ float red[256];
    __shared__ float sc[4];
    __shared__ __align__(16) float gsum[Dd];

    if (tid < 256) red[tid] = d_part_sq[tid];
    __syncthreads();
    for (int s = 128; s; s >>= 1) {
        if (tid < s) red[tid] += red[tid + s];
        __syncthreads();
    }
    if (tid == 0) sc[0] = 1.f / fmaxf(sqrtf(red[0]), 1e-12f);
    __syncthreads();
    if (tid < 256) red[tid] = d_part_mv[tid];
    __syncthreads();
    for (int s = 128; s; s >>= 1) {
        if (tid < s) red[tid] += red[tid + s];
        __syncthreads();
    }
    if (tid == 0) sc[1] = red[0];
    __syncthreads();

    const float inv_norm = sc[0];
    for (int d = tid; d < Dd; d += 640) {
        float v = d_ghat[d] * inv_norm;
#pragma unroll
        for (int r = 1; r < Rr; r++) v += goals[(size_t)r * Dd + d];
        gsum[d] = v;
    }
    __syncthreads();

    if (warp < NAa) {
        float v = wdot<16>((const float4*)(d_T + (size_t)warp * Dd),
                           (const float4*)gsum, lane);
        if (!lane) out[warp] = v;
    } else if (warp == NAa) {
        // last cosine (r = 9, goal = g)
        const float* st = states + (size_t)Rr * Dd;
        float num = 0.f, dd = 0.f, gg = 0.f;
        for (int d = lane; d < Dd; d += 32) {
            float diff = d_s[d] - st[d];
            float go = d_ghat[d] * inv_norm;
            num = fmaf(diff, go, num);
            dd = fmaf(diff, diff, dd);
            gg = fmaf(go, go, gg);
        }
#pragma unroll
        for (int o = 16; o; o >>= 1) {
            num += __shfl_xor_sync(0xffffffffu, num, o);
            dd += __shfl_xor_sync(0xffffffffu, dd, o);
            gg += __shfl_xor_sync(0xffffffffu, gg, o);
        }
        if (!lane)
            sc[2] = num / (fmaxf(sqrtf(dd), 1e-8f) * fmaxf(sqrtf(gg), 1e-8f));
    }
    __syncthreads();
    if (tid == 0) {
        float cs = sc[2];
#pragma unroll
        for (int r = 0; r < Rr - 1; r++) cs += d_cosv[r];
        out[18] = 2048.f * cs * 0.1f;
        out[19] = d_wval;
        out[20] = sc[1] + bmv[0];
    }
}

// ---------------- launch ------------------------------------------------------
extern "C" void kernel_launch(void* const* d_in, const int* in_sizes, int n_in,
                              void* d_out, int out_size) {
    const float* x      = (const float*)d_in[0];
    const float* Wp     = (const float*)d_in[1];
    const float* bp     = (const float*)d_in[2];
    const float* Wms    = (const float*)d_in[3];
    const float* bms    = (const float*)d_in[4];
    const float* Wih_m  = (const float*)d_in[5];
    const float* Whh_m  = (const float*)d_in[6];
    const float* bih_m  = (const float*)d_in[7];
    const float* bhh_m  = (const float*)d_in[8];
    const float* hn_m   = (const float*)d_in[9];
    const float* cn_m   = (const float*)d_in[10];
    const float* Wmv    = (const float*)d_in[11];
    const float* bmv    = (const float*)d_in[12];
    const float* Wih_w  = (const float*)d_in[13];
    const float* Whh_w  = (const float*)d_in[14];
    const float* bih_w  = (const float*)d_in[15];
    const float* bhh_w  = (const float*)d_in[16];
    const float* hn_w   = (const float*)d_in[17];
    const float* cn_w   = (const float*)d_in[18];
    const float* Wphi   = (const float*)d_in[19];
    const float* Wc     = (const float*)d_in[20];
    const float* bc     = (const float*)d_in[21];
    const float* states = (const float*)d_in[22];
    const float* goals  = (const float*)d_in[23];
    const int*   tick   = (const int*)d_in[24];
    float* out = (float*)d_out;

    k2_wave<<<400, 256>>>(x, Wp, bp, Wms, bms, Wih_w, Whh_w, bih_w, bhh_w,
                          hn_w, cn_w);
    k3_wave<<<276, 256>>>(Wih_m, Whh_m, bih_m, bhh_m, hn_m, cn_m, Wmv, Wphi,
                          goals, states, Wc, bc, tick);
    k4_final<<<1, 640>>>(goals, states, bmv, out);
}